// round 13
// baseline (speedup 1.0000x reference)
#include <cuda_runtime.h>
#include <cstdint>
#include <math.h>

// ---- smem float offsets (feature+attn kernel) ----
#define OH2   0       // h halo 14*128 = 1792
#define OX2   1792    // x halo 14*16 = 224
#define OZT2  2016    // zt 14*64 = 896
#define OWHH2 2912    // wh 14*64 = 896
#define OC2   3808    // gemm partials 4*14*64 = 3584
#define OSI   7392    // si 8*32
#define OSJ   7648    // sj 14*32 = 448
#define OSDP  8096    // 4*32
#define OBM   8224    // 32
#define OWM2  8256    // 32
#define OU1   8288    // 14 (pad 16)
#define OU2   8304    // 14 (pad 16)
#define OES   8320    // 64
#define OAT   8384    // 64
#define OCS   8448    // cs 8*128 = 1024
#define OZR   9472    // z 8*64
#define ONRM  9984    // 32
#define ORED  10016   // 8
#define SMEMA 10048   // kernel A floats (~39KB)
// ---- logits kernel layout ----
// B fragments: 2048 float4 (8192 floats); colPart 512; tslot after
#define CPART 8192
#define SMEMB 8712    // ~34KB

// ---------------- scratch (device globals) ----------------
__device__ float  g_qhi[2048*64];
__device__ float  g_qlo[2048*64];
__device__ float4 g_kfrag[2048*32];   // packed {b0hi,b1hi,b0lo,b1lo} per (col,S,j)
__device__ float g_rowsum[2048];
__device__ float g_colsum[2048];
__device__ float g_diag[2048];
__device__ float g_meanpart[256*64];
__device__ float g_timepart[256];
__device__ float g_znfirst[256*64];
__device__ float g_znlast[256*64];
__device__ unsigned int g_done = 0;
__device__ unsigned int g_tile = 0;

// Fast exp on FMA pipe (cephes exp2f poly); |x| <= ~80.
__device__ __forceinline__ float fexp(float x){
    float y = x * 1.44269504088896341f;
    float n = rintf(y);
    float f = y - n;
    float p = 1.535336188319500e-4f;
    p = fmaf(p, f, 1.339887440266574e-3f);
    p = fmaf(p, f, 9.618437357674640e-3f);
    p = fmaf(p, f, 5.550332471162809e-2f);
    p = fmaf(p, f, 2.402264791363012e-1f);
    p = fmaf(p, f, 6.931472028550421e-1f);
    p = fmaf(p, f, 1.0f);
    int e = (int)n;
    return p * __int_as_float((e + 127) << 23);
}

__device__ __forceinline__ float tf32hi(float x){
    uint32_t u;
    asm("cvt.rna.tf32.f32 %0, %1;" : "=r"(u) : "f"(x));
    return __uint_as_float(u);
}

__device__ __forceinline__ void mma8(float* d, float4 a, uint32_t b0, uint32_t b1){
    asm volatile(
        "mma.sync.aligned.m16n8k8.row.col.f32.tf32.tf32.f32 "
        "{%0,%1,%2,%3}, {%4,%5,%6,%7}, {%8,%9}, {%0,%1,%2,%3};\n"
        : "+f"(d[0]), "+f"(d[1]), "+f"(d[2]), "+f"(d[3])
        : "r"(__float_as_uint(a.x)), "r"(__float_as_uint(a.y)),
          "r"(__float_as_uint(a.z)), "r"(__float_as_uint(a.w)),
          "r"(b0), "r"(b1));
}

// ======================= KERNEL A: features + attention ====================
__global__ void __launch_bounds__(256, 3)
feat_kernel(const float* __restrict__ h,      const float* __restrict__ x_raw,
            const float* __restrict__ W_in,   const float* __restrict__ b_in,
            const float* __restrict__ dt_emb, const float* __restrict__ Wm1,
            const float* __restrict__ bm1,    const float* __restrict__ Wm2,
            const float* __restrict__ bm2,    const float* __restrict__ Wg,
            const float* __restrict__ a1,     const float* __restrict__ a2,
            const float* __restrict__ Wf,     const float* __restrict__ bf)
{
    extern __shared__ float sm[];

    const int tid  = threadIdx.x;
    const int gb   = blockIdx.x;       // 0..255
    const int lane = tid & 31;
    const int wid  = tid >> 5;
    const int c    = tid & 63;
    const int quad = tid >> 6;
    const int rp   = tid >> 6;

    const int gbase = gb*8;
    const int lo = gbase & ~511, hi = lo + 511;
    const int i0 = gbase & 511;

    if (gb == 0 && tid == 0) g_tile = 0;   // reset steal counter for logits
    if (tid < 8)       g_rowsum[gbase + tid] = 0.f;
    else if (tid < 16) g_colsum[gbase + tid - 8] = 0.f;

    // stage h (14 halo rows) and x (14), clamped at sequence edges
    for (int idx = tid; idx < 448; idx += 256){
        int hr = idx >> 5, p = idx & 31;
        int gr = gbase - 3 + hr; gr = gr < lo ? lo : (gr > hi ? hi : gr);
        ((float4*)(sm + OH2))[idx] = ((const float4*)h)[gr*32 + p];
    }
    if (tid < 56){
        int hr = tid >> 2, p = tid & 3;
        int gr = gbase - 3 + hr; gr = gr < lo ? lo : (gr > hi ? hi : gr);
        ((float4*)(sm + OX2))[tid] = ((const float4*)x_raw)[gr*4 + p];
    }
    if (tid >= 64 && tid < 192){
        int t = (tid - 64) >> 5, m = tid & 31;
        float s = 0.f;
        #pragma unroll
        for (int e = 0; e < 8; e++)
            s = fmaf(dt_emb[t*8 + e], Wm1[(32 + e)*32 + m], s);
        sm[OSDP + (tid - 64)] = s;
    } else if (tid >= 192 && tid < 224) sm[OBM  + tid - 192] = bm1[tid - 192];
    else if (tid >= 224)                sm[OWM2 + tid - 224] = Wm2[tid - 224];
    const float bm2v = bm2[0];
    __syncthreads();

    // GEMM1 partials: zt_pre = h @ W_in, 14 rows, quad-split K
    {
        float acc[14];
        #pragma unroll
        for (int r = 0; r < 14; r++) acc[r] = 0.f;
        const float4* H4 = (const float4*)(sm + OH2);
        #pragma unroll
        for (int kk = 0; kk < 8; kk++){
            int kb = quad*32 + kk*4;
            float w0 = W_in[(kb+0)*64 + c];
            float w1 = W_in[(kb+1)*64 + c];
            float w2 = W_in[(kb+2)*64 + c];
            float w3 = W_in[(kb+3)*64 + c];
            #pragma unroll
            for (int r = 0; r < 14; r++){
                float4 v = H4[r*32 + (kb>>2)];
                acc[r] = fmaf(w0, v.x, fmaf(w1, v.y, fmaf(w2, v.z, fmaf(w3, v.w, acc[r]))));
            }
        }
        #pragma unroll
        for (int r = 0; r < 14; r++) sm[OC2 + quad*896 + r*64 + c] = acc[r];
    }
    // si (center 8) / sj (14): warp t -> halo row t
    for (int t = wid; t < 14; t += 8){
        const float* xp = sm + OX2 + t*16;
        float si = 0.f, sj = 0.f;
        #pragma unroll
        for (int q = 0; q < 16; q++){
            float xv = xp[q];
            si = fmaf(xv, Wm1[q*32 + lane], si);
            sj = fmaf(xv, Wm1[(16+q)*32 + lane], sj);
        }
        sm[OSJ + t*32 + lane] = sj;
        if (t >= 3 && t < 11) sm[OSI + (t-3)*32 + lane] = si;
    }
    __syncthreads();

    // zt combine (14 rows)
    {
        float bi = b_in[c];
        for (int r = rp; r < 14; r += 4){
            float z = bi + sm[OC2 + 0*896 + r*64 + c] + sm[OC2 + 1*896 + r*64 + c]
                         + sm[OC2 + 2*896 + r*64 + c] + sm[OC2 + 3*896 + r*64 + c];
            sm[OZT2 + r*64 + c] = fmaxf(z, 0.f);
        }
    }
    __syncthreads();

    // GEMM2 partials: wh = zt @ Wg, 14 rows, K=64
    {
        float acc[14];
        #pragma unroll
        for (int r = 0; r < 14; r++) acc[r] = 0.f;
        const float4* Z4 = (const float4*)(sm + OZT2);
        #pragma unroll
        for (int kk = 0; kk < 4; kk++){
            int kb = quad*16 + kk*4;
            float w0 = Wg[(kb+0)*64 + c];
            float w1 = Wg[(kb+1)*64 + c];
            float w2 = Wg[(kb+2)*64 + c];
            float w3 = Wg[(kb+3)*64 + c];
            #pragma unroll
            for (int r = 0; r < 14; r++){
                float4 v = Z4[r*16 + (kb>>2)];
                acc[r] = fmaf(w0, v.x, fmaf(w1, v.y, fmaf(w2, v.z, fmaf(w3, v.w, acc[r]))));
            }
        }
        #pragma unroll
        for (int r = 0; r < 14; r++) sm[OC2 + quad*896 + r*64 + c] = acc[r];
    }
    __syncthreads();
    {
        for (int r = rp; r < 14; r += 4){
            float whv = sm[OC2 + 0*896 + r*64 + c] + sm[OC2 + 1*896 + r*64 + c]
                      + sm[OC2 + 2*896 + r*64 + c] + sm[OC2 + 3*896 + r*64 + c];
            sm[OWHH2 + r*64 + c] = whv;
        }
    }
    __syncthreads();

    // u1/u2 for 14 halo rows
    for (int t = wid; t < 14; t += 8){
        const float* whp = sm + OWHH2 + t*64;
        float v1 = whp[lane]*a1[lane] + whp[lane+32]*a1[lane+32];
        float v2 = whp[lane]*a2[lane] + whp[lane+32]*a2[lane+32];
        #pragma unroll
        for (int s = 16; s > 0; s >>= 1){
            v1 += __shfl_down_sync(0xffffffffu, v1, s);
            v2 += __shfl_down_sync(0xffffffffu, v2, s);
        }
        if (lane == 0){
            sm[OU1 + t] = v1;
            sm[OU2 + t] = v2;
        }
    }
    __syncthreads();

    // bias: 56 warp-tasks (center row r, offset o)
    for (int t = wid; t < 56; t += 8){
        int r = t / 7, o = t - r*7;
        int jl = i0 + r - 3 + o;
        int jj = r + o;                    // halo index of j
        int dtv = 3 - o; if (dtv < 0) dtv = 0;
        float v = sm[OSI + r*32 + lane] + sm[OSJ + jj*32 + lane]
                + sm[OSDP + dtv*32 + lane] + sm[OBM + lane];
        float p = v > 0.f ? v * sm[OWM2 + lane] : 0.f;
        #pragma unroll
        for (int s = 16; s > 0; s >>= 1) p += __shfl_down_sync(0xffffffffu, p, s);
        if (lane == 0){
            float e = -1e30f;
            if (jl >= 0 && jl < 512){
                float u = sm[OU1 + r + 3] + sm[OU2 + jj];
                float lr = u > 0.f ? u : 0.2f*u;
                e = lr + p + bm2v - 0.2f*(float)dtv;
            }
            sm[OES + r*8 + o] = e;
        }
    }
    __syncthreads();
    if (tid < 8){
        float mx = -1e30f;
        #pragma unroll
        for (int o = 0; o < 7; o++) mx = fmaxf(mx, sm[OES + tid*8 + o]);
        float sum = 0.f, ex[7];
        #pragma unroll
        for (int o = 0; o < 7; o++){
            float e = sm[OES + tid*8 + o];
            ex[o] = e > -1e29f ? fexp(e - mx) : 0.f;
            sum += ex[o];
        }
        float inv = 1.f / sum;
        #pragma unroll
        for (int o = 0; o < 7; o++) sm[OAT + tid*8 + o] = ex[o]*inv;
    }
    __syncthreads();

    // zg = elu(attn @ wh); cs = [zt | zg]  (center rows)
    {
        #pragma unroll
        for (int s = 0; s < 2; s++){
            int rr = rp + s*4;
            float acc = 0.f;
            #pragma unroll
            for (int o = 0; o < 7; o++)
                acc = fmaf(sm[OAT + rr*8 + o], sm[OWHH2 + (rr+o)*64 + c], acc);
            float zg = acc > 0.f ? acc : fexp(acc) - 1.f;
            sm[OCS + rr*128 + 64 + c] = zg;
            sm[OCS + rr*128 + c]      = sm[OZT2 + (rr+3)*64 + c];
        }
    }
    __syncthreads();

    // GEMM3 partials: z = cs @ Wf, 8 center rows, K=128
    {
        float acc[8] = {0,0,0,0,0,0,0,0};
        const float4* C4 = (const float4*)(sm + OCS);
        #pragma unroll
        for (int kk = 0; kk < 8; kk++){
            int kb = quad*32 + kk*4;
            float w0 = Wf[(kb+0)*64 + c];
            float w1 = Wf[(kb+1)*64 + c];
            float w2 = Wf[(kb+2)*64 + c];
            float w3 = Wf[(kb+3)*64 + c];
            #pragma unroll
            for (int r = 0; r < 8; r++){
                float4 v = C4[r*32 + (kb>>2)];
                acc[r] = fmaf(w0, v.x, fmaf(w1, v.y, fmaf(w2, v.z, fmaf(w3, v.w, acc[r]))));
            }
        }
        #pragma unroll
        for (int r = 0; r < 8; r++) sm[OC2 + quad*512 + r*64 + c] = acc[r];
    }
    __syncthreads();
    {
        float bfc = bf[c];
        #pragma unroll
        for (int s = 0; s < 2; s++){
            int rr = rp + s*4;
            float z = bfc + sm[OC2 + 0*512 + rr*64 + c] + sm[OC2 + 1*512 + rr*64 + c]
                          + sm[OC2 + 2*512 + rr*64 + c] + sm[OC2 + 3*512 + rr*64 + c];
            sm[OZR + rr*64 + c] = fmaxf(z, 0.f);
        }
    }
    __syncthreads();

    // norms: 32 warp-tasks (8 rows x {z, zt, zg, zt.zg})
    for (int t = wid; t < 32; t += 8){
        int r = t >> 2, which = t & 3;
        float v;
        if (which == 0){
            float x1 = sm[OZR + r*64 + lane], x2 = sm[OZR + r*64 + lane + 32];
            v = x1*x1 + x2*x2;
        } else if (which == 1){
            float x1 = sm[OZT2 + (r+3)*64 + lane], x2 = sm[OZT2 + (r+3)*64 + lane + 32];
            v = x1*x1 + x2*x2;
        } else if (which == 2){
            float x1 = sm[OCS + r*128 + 64 + lane], x2 = sm[OCS + r*128 + 96 + lane];
            v = x1*x1 + x2*x2;
        } else {
            v = sm[OZT2 + (r+3)*64 + lane]      * sm[OCS + r*128 + 64 + lane]
              + sm[OZT2 + (r+3)*64 + lane + 32] * sm[OCS + r*128 + 96 + lane];
        }
        #pragma unroll
        for (int s = 16; s > 0; s >>= 1) v += __shfl_down_sync(0xffffffffu, v, s);
        if (lane == 0) sm[ONRM + r*4 + which] = v;
    }
    __syncthreads();

    // outputs: q hi/lo, diag
    {
        #pragma unroll
        for (int s = 0; s < 2; s++){
            int rr = rp + s*4;
            float invzt = 1.f / fmaxf(sqrtf(sm[ONRM + rr*4 + 1]), 1e-8f);
            float invzg = 1.f / fmaxf(sqrtf(sm[ONRM + rr*4 + 2]), 1e-8f);
            int gr = gbase + rr;
            float qv = sm[OZT2 + (rr+3)*64 + c] * invzt;
            float qh = tf32hi(qv);
            g_qhi[gr*64 + c] = qh;
            g_qlo[gr*64 + c] = tf32hi(qv - qh);
            if (c == 0) g_diag[gr] = 10.f * sm[ONRM + rr*4 + 3] * invzt * invzg;
        }
    }
    // k fragments: one float4 per thread (row, S, j)
    {
        int row = tid >> 5;           // 0..7
        int S   = (tid >> 2) & 7;
        int j   = tid & 3;
        float invzg = 1.f / fmaxf(sqrtf(sm[ONRM + row*4 + 2]), 1e-8f);
        float b0 = sm[OCS + row*128 + 64 + S*8 + j]     * invzg;
        float b1 = sm[OCS + row*128 + 64 + S*8 + 4 + j] * invzg;
        float b0h = tf32hi(b0), b1h = tf32hi(b1);
        g_kfrag[(gbase + row)*32 + S*4 + j] =
            make_float4(b0h, b1h, tf32hi(b0 - b0h), tf32hi(b1 - b1h));
    }
    if (tid < 64){
        float ms = 0.f;
        float zn0 = 0.f, zn7 = 0.f;
        #pragma unroll
        for (int r = 0; r < 8; r++){
            float invz = 1.f / fmaxf(sqrtf(sm[ONRM + r*4]), 1e-8f);
            float zn = sm[OZR + r*64 + tid] * invz;
            ms += zn;
            if (r == 0) zn0 = zn;
            if (r == 7) zn7 = zn;
        }
        g_meanpart[gb*64 + tid] = ms;
        g_znfirst[gb*64 + tid]  = zn0;
        g_znlast[gb*64 + tid]   = zn7;
    }
    if (wid < 7){
        int r = wid;
        float iz1 = 1.f / fmaxf(sqrtf(sm[ONRM + r*4]), 1e-8f);
        float iz2 = 1.f / fmaxf(sqrtf(sm[ONRM + (r+1)*4]), 1e-8f);
        float d = sm[OZR + r*64 + lane]      * sm[OZR + (r+1)*64 + lane]
                + sm[OZR + r*64 + lane + 32] * sm[OZR + (r+1)*64 + lane + 32];
        #pragma unroll
        for (int s = 16; s > 0; s >>= 1) d += __shfl_down_sync(0xffffffffu, d, s);
        if (lane == 0){
            float dd = 1.f - d*iz1*iz2;
            sm[ORED + r] = dd*dd;
        }
    }
    __syncthreads();
    if (tid == 0){
        float ts = 0.f;
        #pragma unroll
        for (int r = 0; r < 7; r++) ts += sm[ORED + r];
        g_timepart[gb] = ts;
    }
}

// ================ KERNEL B: cross pairs + tensor logits + final ============
__global__ void __launch_bounds__(256, 3)
logits_kernel(float* __restrict__ out)
{
    extern __shared__ float sm[];
    __shared__ unsigned int lastFlag;
    __shared__ int tslot;

    const int tid  = threadIdx.x;
    const int bid  = blockIdx.x;
    const int G    = gridDim.x;
    const int lane = tid & 31;
    const int wid  = tid >> 5;
    const int c    = tid & 63;
    const int quad = tid >> 6;

    // cross time-pairs (grid-stride over 256 groups)
    for (int gb = bid; gb < 256; gb += G){
        if ((gb & 63) != 63 && wid == 0){
            float d = g_znlast[gb*64 + lane]      * g_znfirst[(gb+1)*64 + lane]
                    + g_znlast[gb*64 + lane + 32] * g_znfirst[(gb+1)*64 + lane + 32];
            #pragma unroll
            for (int s = 16; s > 0; s >>= 1) d += __shfl_down_sync(0xffffffffu, d, s);
            if (lane == 0){
                float dd = 1.f - d;
                g_timepart[gb] += dd*dd;
            }
        }
    }

    // logits: 512 tiles of 128 rows x 64 cols; warp = 16 rows x 64 cols
    float4* BV = (float4*)sm;
    float* colPart = sm + CPART;

    while (true){
        __syncthreads();
        if (tid == 0) tslot = (int)atomicAdd(&g_tile, 1u);
        __syncthreads();
        int ti = tslot;
        if (ti >= 512) break;
        const int rb = (ti & 15) << 7, cb = (ti >> 4) << 6;

        // stage B fragments: pure copy from precomputed g_kfrag (64 cols)
        #pragma unroll
        for (int it = 0; it < 8; it++){
            int e = it*256 + tid;
            int n = e >> 8, S = (e >> 5) & 7, colq = (e >> 2) & 7, j = e & 3;
            BV[e] = g_kfrag[(cb + n*8 + colq)*32 + S*4 + j];
        }
        __syncthreads();

        float acc[8][4];
        #pragma unroll
        for (int n = 0; n < 8; n++){
            acc[n][0] = 0.f; acc[n][1] = 0.f; acc[n][2] = 0.f; acc[n][3] = 0.f;
        }

        const int abase = (rb + wid*16 + (lane >> 2))*64 + (lane & 3);
        const float* qh0 = &g_qhi[abase];
        const float* ql0 = &g_qlo[abase];

        #pragma unroll
        for (int S = 0; S < 8; S++){
            int off = S*8;
            float4 ah = make_float4(qh0[off], qh0[off + 512], qh0[off + 4], qh0[off + 516]);
            float4 al = make_float4(ql0[off], ql0[off + 512], ql0[off + 4], ql0[off + 516]);
            #pragma unroll
            for (int n = 0; n < 8; n++){
                float4 bb = BV[(n*8 + S)*32 + lane];
                uint32_t b0h = __float_as_uint(bb.x), b1h = __float_as_uint(bb.y);
                uint32_t b0l = __float_as_uint(bb.z), b1l = __float_as_uint(bb.w);
                mma8(acc[n], ah, b0h, b1h);
                mma8(acc[n], ah, b0l, b1l);
                mma8(acc[n], al, b0h, b1h);
            }
        }

        // epilogue: exp + row/col sums
        float rlo = 0.f, rhi = 0.f;
        #pragma unroll
        for (int n = 0; n < 8; n++){
            float e0 = fexp(acc[n][0] * 10.f);
            float e1 = fexp(acc[n][1] * 10.f);
            float e2 = fexp(acc[n][2] * 10.f);
            float e3 = fexp(acc[n][3] * 10.f);
            rlo += e0 + e1; rhi += e2 + e3;
            float ca = e0 + e2, cbv = e1 + e3;
            #pragma unroll
            for (int o = 4; o < 32; o <<= 1){
                ca  += __shfl_xor_sync(0xffffffffu, ca,  o);
                cbv += __shfl_xor_sync(0xffffffffu, cbv, o);
            }
            if (lane < 4){
                colPart[wid*64 + n*8 + 2*lane]     = ca;
                colPart[wid*64 + n*8 + 2*lane + 1] = cbv;
            }
        }
        rlo += __shfl_xor_sync(0xffffffffu, rlo, 1);
        rlo += __shfl_xor_sync(0xffffffffu, rlo, 2);
        rhi += __shfl_xor_sync(0xffffffffu, rhi, 1);
        rhi += __shfl_xor_sync(0xffffffffu, rhi, 2);
        if ((lane & 3) == 0){
            atomicAdd(&g_rowsum[rb + wid*16 + (lane >> 2)],     rlo);
            atomicAdd(&g_rowsum[rb + wid*16 + 8 + (lane >> 2)], rhi);
        }
        __syncthreads();
        if (tid < 64){
            float s2 = 0.f;
            #pragma unroll
            for (int w2 = 0; w2 < 8; w2++) s2 += colPart[w2*64 + tid];
            atomicAdd(&g_colsum[cb + tid], s2);
        }
    }

    // ---- final combine: last block ----
    __threadfence();
    __syncthreads();
    if (tid == 0){
        unsigned t = atomicAdd(&g_done, 1u);
        lastFlag = (t == (unsigned)G - 1u) ? 1u : 0u;
    }
    __syncthreads();
    if (lastFlag){
        float ms = 0.f;
        for (int blk = quad; blk < 256; blk += 4)
            ms += __ldcg(&g_meanpart[blk*64 + c]);
        __syncthreads();
        sm[tid] = ms;
        __syncthreads();
        if (tid < 64){
            float Mv = sm[tid] + sm[64+tid] + sm[128+tid] + sm[192+tid];
            sm[256 + tid] = Mv*Mv;
        }
        __syncthreads();

        float tv = __ldcg(&g_timepart[tid]);
        float s = 0.f;
        for (int r = tid; r < 2048; r += 256)
            s += __logf(__ldcg(&g_rowsum[r])) + __logf(__ldcg(&g_colsum[r]))
               - 2.f*__ldcg(&g_diag[r]);
        sm[512 + tid] = tv;
        sm[768 + tid] = s;
        __syncthreads();
        for (int st = 128; st > 0; st >>= 1){
            if (tid < st){
                sm[512+tid] += sm[512+tid+st];
                sm[768+tid] += sm[768+tid+st];
            }
            __syncthreads();
        }
        if (tid == 0){
            float nm2 = 0.f;
            #pragma unroll
            for (int i = 0; i < 64; i++) nm2 += sm[256 + i];
            float normM = sqrtf(nm2);
            float l_con = 0.5f * sm[768] / 2048.f;
            float l_sc  = -normM / 2048.f;
            float l_t   =  sm[512] / 2044.f;
            out[0] = l_con + l_sc + l_t;
            out[1] = l_con;
            out[2] = l_sc;
            out[3] = l_t;
            g_done = 0;   // reset for next graph replay
        }
    }
}

// ---------------- launch ----------------
extern "C" void kernel_launch(void* const* d_in, const int* in_sizes, int n_in,
                              void* d_out, int out_size){
    const float* h      = (const float*)d_in[0];
    const float* x_raw  = (const float*)d_in[1];
    const float* W_in   = (const float*)d_in[2];
    const float* b_in   = (const float*)d_in[3];
    const float* dt_emb = (const float*)d_in[4];
    const float* Wm1    = (const float*)d_in[5];
    const float* bm1    = (const float*)d_in[6];
    const float* bm2    = (const float*)d_in[8];
    const float* Wm2    = (const float*)d_in[7];
    const float* Wg     = (const float*)d_in[9];
    const float* a1     = (const float*)d_in[10];
    const float* a2     = (const float*)d_in[11];
    const float* Wf     = (const float*)d_in[12];
    const float* bf     = (const float*)d_in[13];
    float* out = (float*)d_out;

    const int SMA = SMEMA * 4;
    const int SMB = SMEMB * 4;
    cudaFuncSetAttribute(feat_kernel,   cudaFuncAttributeMaxDynamicSharedMemorySize, SMA);
    cudaFuncSetAttribute(logits_kernel, cudaFuncAttributeMaxDynamicSharedMemorySize, SMB);

    int dev = 0; cudaGetDevice(&dev);
    int sms = 0;
    cudaDeviceGetAttribute(&sms, cudaDevAttrMultiProcessorCount, dev);
    if (sms <= 0) sms = 148;

    int maxB = 2;
    cudaOccupancyMaxActiveBlocksPerMultiprocessor(&maxB, logits_kernel, 256, SMB);
    if (maxB < 1) maxB = 1;
    if (maxB > 3) maxB = 3;
    int GB = sms * maxB;          // uniform blocks/SM; work-stealing balances tiles

    feat_kernel<<<256, 256, SMA>>>(h, x_raw, W_in, b_in, dt_emb, Wm1, bm1, Wm2,
                                   bm2, Wg, a1, a2, Wf, bf);
    logits_kernel<<<GB, 256, SMB>>>(out);
}

// round 14
// speedup vs baseline: 1.2506x; 1.2506x over previous
#include <cuda_runtime.h>
#include <cstdint>
#include <math.h>

// ---- smem float offsets (feature+attn kernel) ----
#define OH2   0       // h halo 14*128 = 1792
#define OX2   1792    // x halo 14*16 = 224
#define OZT2  2016    // zt 14*64 = 896
#define OWHH2 2912    // wh 14*64 = 896
#define OC2   3808    // gemm partials 4*14*64 = 3584
#define OSI   7392    // si 8*32
#define OSJ   7648    // sj 14*32 = 448
#define OSDP  8096    // 4*32
#define OBM   8224    // 32
#define OWM2  8256    // 32
#define OU1   8288    // 14 (pad 16)
#define OU2   8304    // 14 (pad 16)
#define OES   8320    // 64
#define OAT   8384    // 64
#define OCS   8448    // cs 8*128 = 1024
#define OZR   9472    // z 8*64
#define ONRM  9984    // 32
#define ORED  10016   // 8
#define SMEMA 10048   // kernel A floats (~39KB)
// ---- logits kernel layout ----
#define CPART 16384   // colPart 8*128
#define SMEMB 17408   // kernel B floats (68KB)

// ---------------- scratch (device globals) ----------------
__device__ float4 g_qfrag[2048*32];   // {a0hi,a1hi,a0lo,a1lo} per (row,S,j): k=S*8+j, S*8+4+j
__device__ float4 g_kfrag[2048*32];   // {b0hi,b1hi,b0lo,b1lo} per (col,S,j)
__device__ float g_rowsum[2048];
__device__ float g_colsum[2048];
__device__ float g_diag[2048];
__device__ float g_meanpart[256*64];
__device__ float g_timepart[256];
__device__ float g_znfirst[256*64];
__device__ float g_znlast[256*64];
__device__ unsigned int g_done = 0;

// Fast exp on FMA pipe (cephes exp2f poly); |x| <= ~80.
__device__ __forceinline__ float fexp(float x){
    float y = x * 1.44269504088896341f;
    float n = rintf(y);
    float f = y - n;
    float p = 1.535336188319500e-4f;
    p = fmaf(p, f, 1.339887440266574e-3f);
    p = fmaf(p, f, 9.618437357674640e-3f);
    p = fmaf(p, f, 5.550332471162809e-2f);
    p = fmaf(p, f, 2.402264791363012e-1f);
    p = fmaf(p, f, 6.931472028550421e-1f);
    p = fmaf(p, f, 1.0f);
    int e = (int)n;
    return p * __int_as_float((e + 127) << 23);
}

__device__ __forceinline__ float tf32hi(float x){
    uint32_t u;
    asm("cvt.rna.tf32.f32 %0, %1;" : "=r"(u) : "f"(x));
    return __uint_as_float(u);
}

__device__ __forceinline__ void mma8(float* d, float4 a, uint32_t b0, uint32_t b1){
    asm volatile(
        "mma.sync.aligned.m16n8k8.row.col.f32.tf32.tf32.f32 "
        "{%0,%1,%2,%3}, {%4,%5,%6,%7}, {%8,%9}, {%0,%1,%2,%3};\n"
        : "+f"(d[0]), "+f"(d[1]), "+f"(d[2]), "+f"(d[3])
        : "r"(__float_as_uint(a.x)), "r"(__float_as_uint(a.y)),
          "r"(__float_as_uint(a.z)), "r"(__float_as_uint(a.w)),
          "r"(b0), "r"(b1));
}

// ======================= KERNEL A: features + attention ====================
__global__ void __launch_bounds__(256, 3)
feat_kernel(const float* __restrict__ h,      const float* __restrict__ x_raw,
            const float* __restrict__ W_in,   const float* __restrict__ b_in,
            const float* __restrict__ dt_emb, const float* __restrict__ Wm1,
            const float* __restrict__ bm1,    const float* __restrict__ Wm2,
            const float* __restrict__ bm2,    const float* __restrict__ Wg,
            const float* __restrict__ a1,     const float* __restrict__ a2,
            const float* __restrict__ Wf,     const float* __restrict__ bf)
{
    extern __shared__ float sm[];

    const int tid  = threadIdx.x;
    const int gb   = blockIdx.x;       // 0..255
    const int lane = tid & 31;
    const int wid  = tid >> 5;
    const int c    = tid & 63;
    const int quad = tid >> 6;
    const int rp   = tid >> 6;

    const int gbase = gb*8;
    const int lo = gbase & ~511, hi = lo + 511;
    const int i0 = gbase & 511;

    if (tid < 8)       g_rowsum[gbase + tid] = 0.f;
    else if (tid < 16) g_colsum[gbase + tid - 8] = 0.f;

    // stage h (14 halo rows) and x (14), clamped at sequence edges
    for (int idx = tid; idx < 448; idx += 256){
        int hr = idx >> 5, p = idx & 31;
        int gr = gbase - 3 + hr; gr = gr < lo ? lo : (gr > hi ? hi : gr);
        ((float4*)(sm + OH2))[idx] = ((const float4*)h)[gr*32 + p];
    }
    if (tid < 56){
        int hr = tid >> 2, p = tid & 3;
        int gr = gbase - 3 + hr; gr = gr < lo ? lo : (gr > hi ? hi : gr);
        ((float4*)(sm + OX2))[tid] = ((const float4*)x_raw)[gr*4 + p];
    }
    if (tid >= 64 && tid < 192){
        int t = (tid - 64) >> 5, m = tid & 31;
        float s = 0.f;
        #pragma unroll
        for (int e = 0; e < 8; e++)
            s = fmaf(dt_emb[t*8 + e], Wm1[(32 + e)*32 + m], s);
        sm[OSDP + (tid - 64)] = s;
    } else if (tid >= 192 && tid < 224) sm[OBM  + tid - 192] = bm1[tid - 192];
    else if (tid >= 224)                sm[OWM2 + tid - 224] = Wm2[tid - 224];
    const float bm2v = bm2[0];
    __syncthreads();

    // GEMM1 partials: zt_pre = h @ W_in, 14 rows, quad-split K
    {
        float acc[14];
        #pragma unroll
        for (int r = 0; r < 14; r++) acc[r] = 0.f;
        const float4* H4 = (const float4*)(sm + OH2);
        #pragma unroll
        for (int kk = 0; kk < 8; kk++){
            int kb = quad*32 + kk*4;
            float w0 = W_in[(kb+0)*64 + c];
            float w1 = W_in[(kb+1)*64 + c];
            float w2 = W_in[(kb+2)*64 + c];
            float w3 = W_in[(kb+3)*64 + c];
            #pragma unroll
            for (int r = 0; r < 14; r++){
                float4 v = H4[r*32 + (kb>>2)];
                acc[r] = fmaf(w0, v.x, fmaf(w1, v.y, fmaf(w2, v.z, fmaf(w3, v.w, acc[r]))));
            }
        }
        #pragma unroll
        for (int r = 0; r < 14; r++) sm[OC2 + quad*896 + r*64 + c] = acc[r];
    }
    // si (center 8) / sj (14): warp t -> halo row t
    for (int t = wid; t < 14; t += 8){
        const float* xp = sm + OX2 + t*16;
        float si = 0.f, sj = 0.f;
        #pragma unroll
        for (int q = 0; q < 16; q++){
            float xv = xp[q];
            si = fmaf(xv, Wm1[q*32 + lane], si);
            sj = fmaf(xv, Wm1[(16+q)*32 + lane], sj);
        }
        sm[OSJ + t*32 + lane] = sj;
        if (t >= 3 && t < 11) sm[OSI + (t-3)*32 + lane] = si;
    }
    __syncthreads();

    // zt combine (14 rows)
    {
        float bi = b_in[c];
        for (int r = rp; r < 14; r += 4){
            float z = bi + sm[OC2 + 0*896 + r*64 + c] + sm[OC2 + 1*896 + r*64 + c]
                         + sm[OC2 + 2*896 + r*64 + c] + sm[OC2 + 3*896 + r*64 + c];
            sm[OZT2 + r*64 + c] = fmaxf(z, 0.f);
        }
    }
    __syncthreads();

    // GEMM2 partials: wh = zt @ Wg, 14 rows, K=64
    {
        float acc[14];
        #pragma unroll
        for (int r = 0; r < 14; r++) acc[r] = 0.f;
        const float4* Z4 = (const float4*)(sm + OZT2);
        #pragma unroll
        for (int kk = 0; kk < 4; kk++){
            int kb = quad*16 + kk*4;
            float w0 = Wg[(kb+0)*64 + c];
            float w1 = Wg[(kb+1)*64 + c];
            float w2 = Wg[(kb+2)*64 + c];
            float w3 = Wg[(kb+3)*64 + c];
            #pragma unroll
            for (int r = 0; r < 14; r++){
                float4 v = Z4[r*16 + (kb>>2)];
                acc[r] = fmaf(w0, v.x, fmaf(w1, v.y, fmaf(w2, v.z, fmaf(w3, v.w, acc[r]))));
            }
        }
        #pragma unroll
        for (int r = 0; r < 14; r++) sm[OC2 + quad*896 + r*64 + c] = acc[r];
    }
    __syncthreads();
    {
        for (int r = rp; r < 14; r += 4){
            float whv = sm[OC2 + 0*896 + r*64 + c] + sm[OC2 + 1*896 + r*64 + c]
                      + sm[OC2 + 2*896 + r*64 + c] + sm[OC2 + 3*896 + r*64 + c];
            sm[OWHH2 + r*64 + c] = whv;
        }
    }
    __syncthreads();

    // u1/u2 for 14 halo rows
    for (int t = wid; t < 14; t += 8){
        const float* whp = sm + OWHH2 + t*64;
        float v1 = whp[lane]*a1[lane] + whp[lane+32]*a1[lane+32];
        float v2 = whp[lane]*a2[lane] + whp[lane+32]*a2[lane+32];
        #pragma unroll
        for (int s = 16; s > 0; s >>= 1){
            v1 += __shfl_down_sync(0xffffffffu, v1, s);
            v2 += __shfl_down_sync(0xffffffffu, v2, s);
        }
        if (lane == 0){
            sm[OU1 + t] = v1;
            sm[OU2 + t] = v2;
        }
    }
    __syncthreads();

    // bias: 56 warp-tasks (center row r, offset o)
    for (int t = wid; t < 56; t += 8){
        int r = t / 7, o = t - r*7;
        int jl = i0 + r - 3 + o;
        int jj = r + o;                    // halo index of j
        int dtv = 3 - o; if (dtv < 0) dtv = 0;
        float v = sm[OSI + r*32 + lane] + sm[OSJ + jj*32 + lane]
                + sm[OSDP + dtv*32 + lane] + sm[OBM + lane];
        float p = v > 0.f ? v * sm[OWM2 + lane] : 0.f;
        #pragma unroll
        for (int s = 16; s > 0; s >>= 1) p += __shfl_down_sync(0xffffffffu, p, s);
        if (lane == 0){
            float e = -1e30f;
            if (jl >= 0 && jl < 512){
                float u = sm[OU1 + r + 3] + sm[OU2 + jj];
                float lr = u > 0.f ? u : 0.2f*u;
                e = lr + p + bm2v - 0.2f*(float)dtv;
            }
            sm[OES + r*8 + o] = e;
        }
    }
    __syncthreads();
    if (tid < 8){
        float mx = -1e30f;
        #pragma unroll
        for (int o = 0; o < 7; o++) mx = fmaxf(mx, sm[OES + tid*8 + o]);
        float sum = 0.f, ex[7];
        #pragma unroll
        for (int o = 0; o < 7; o++){
            float e = sm[OES + tid*8 + o];
            ex[o] = e > -1e29f ? fexp(e - mx) : 0.f;
            sum += ex[o];
        }
        float inv = 1.f / sum;
        #pragma unroll
        for (int o = 0; o < 7; o++) sm[OAT + tid*8 + o] = ex[o]*inv;
    }
    __syncthreads();

    // zg = elu(attn @ wh); cs = [zt | zg]  (center rows)
    {
        #pragma unroll
        for (int s = 0; s < 2; s++){
            int rr = rp + s*4;
            float acc = 0.f;
            #pragma unroll
            for (int o = 0; o < 7; o++)
                acc = fmaf(sm[OAT + rr*8 + o], sm[OWHH2 + (rr+o)*64 + c], acc);
            float zg = acc > 0.f ? acc : fexp(acc) - 1.f;
            sm[OCS + rr*128 + 64 + c] = zg;
            sm[OCS + rr*128 + c]      = sm[OZT2 + (rr+3)*64 + c];
        }
    }
    __syncthreads();

    // GEMM3 partials: z = cs @ Wf, 8 center rows, K=128
    {
        float acc[8] = {0,0,0,0,0,0,0,0};
        const float4* C4 = (const float4*)(sm + OCS);
        #pragma unroll
        for (int kk = 0; kk < 8; kk++){
            int kb = quad*32 + kk*4;
            float w0 = Wf[(kb+0)*64 + c];
            float w1 = Wf[(kb+1)*64 + c];
            float w2 = Wf[(kb+2)*64 + c];
            float w3 = Wf[(kb+3)*64 + c];
            #pragma unroll
            for (int r = 0; r < 8; r++){
                float4 v = C4[r*32 + (kb>>2)];
                acc[r] = fmaf(w0, v.x, fmaf(w1, v.y, fmaf(w2, v.z, fmaf(w3, v.w, acc[r]))));
            }
        }
        #pragma unroll
        for (int r = 0; r < 8; r++) sm[OC2 + quad*512 + r*64 + c] = acc[r];
    }
    __syncthreads();
    {
        float bfc = bf[c];
        #pragma unroll
        for (int s = 0; s < 2; s++){
            int rr = rp + s*4;
            float z = bfc + sm[OC2 + 0*512 + rr*64 + c] + sm[OC2 + 1*512 + rr*64 + c]
                          + sm[OC2 + 2*512 + rr*64 + c] + sm[OC2 + 3*512 + rr*64 + c];
            sm[OZR + rr*64 + c] = fmaxf(z, 0.f);
        }
    }
    __syncthreads();

    // norms: 32 warp-tasks (8 rows x {z, zt, zg, zt.zg})
    for (int t = wid; t < 32; t += 8){
        int r = t >> 2, which = t & 3;
        float v;
        if (which == 0){
            float x1 = sm[OZR + r*64 + lane], x2 = sm[OZR + r*64 + lane + 32];
            v = x1*x1 + x2*x2;
        } else if (which == 1){
            float x1 = sm[OZT2 + (r+3)*64 + lane], x2 = sm[OZT2 + (r+3)*64 + lane + 32];
            v = x1*x1 + x2*x2;
        } else if (which == 2){
            float x1 = sm[OCS + r*128 + 64 + lane], x2 = sm[OCS + r*128 + 96 + lane];
            v = x1*x1 + x2*x2;
        } else {
            v = sm[OZT2 + (r+3)*64 + lane]      * sm[OCS + r*128 + 64 + lane]
              + sm[OZT2 + (r+3)*64 + lane + 32] * sm[OCS + r*128 + 96 + lane];
        }
        #pragma unroll
        for (int s = 16; s > 0; s >>= 1) v += __shfl_down_sync(0xffffffffu, v, s);
        if (lane == 0) sm[ONRM + r*4 + which] = v;
    }
    __syncthreads();

    // diag
    if (tid < 8){
        float invzt = 1.f / fmaxf(sqrtf(sm[ONRM + tid*4 + 1]), 1e-8f);
        float invzg = 1.f / fmaxf(sqrtf(sm[ONRM + tid*4 + 2]), 1e-8f);
        g_diag[gbase + tid] = 10.f * sm[ONRM + tid*4 + 3] * invzt * invzg;
    }
    // q fragments: one float4 per thread (row, S, j) — mirrors k layout
    {
        int row = tid >> 5;           // 0..7
        int S   = (tid >> 2) & 7;
        int j   = tid & 3;
        float invzt = 1.f / fmaxf(sqrtf(sm[ONRM + row*4 + 1]), 1e-8f);
        float q0 = sm[OZT2 + (row+3)*64 + S*8 + j]     * invzt;
        float q1 = sm[OZT2 + (row+3)*64 + S*8 + 4 + j] * invzt;
        float q0h = tf32hi(q0), q1h = tf32hi(q1);
        g_qfrag[(gbase + row)*32 + S*4 + j] =
            make_float4(q0h, q1h, tf32hi(q0 - q0h), tf32hi(q1 - q1h));
    }
    // k fragments: one float4 per thread (row, S, j)
    {
        int row = tid >> 5;           // 0..7
        int S   = (tid >> 2) & 7;
        int j   = tid & 3;
        float invzg = 1.f / fmaxf(sqrtf(sm[ONRM + row*4 + 2]), 1e-8f);
        float b0 = sm[OCS + row*128 + 64 + S*8 + j]     * invzg;
        float b1 = sm[OCS + row*128 + 64 + S*8 + 4 + j] * invzg;
        float b0h = tf32hi(b0), b1h = tf32hi(b1);
        g_kfrag[(gbase + row)*32 + S*4 + j] =
            make_float4(b0h, b1h, tf32hi(b0 - b0h), tf32hi(b1 - b1h));
    }
    if (tid < 64){
        float ms = 0.f;
        float zn0 = 0.f, zn7 = 0.f;
        #pragma unroll
        for (int r = 0; r < 8; r++){
            float invz = 1.f / fmaxf(sqrtf(sm[ONRM + r*4]), 1e-8f);
            float zn = sm[OZR + r*64 + tid] * invz;
            ms += zn;
            if (r == 0) zn0 = zn;
            if (r == 7) zn7 = zn;
        }
        g_meanpart[gb*64 + tid] = ms;
        g_znfirst[gb*64 + tid]  = zn0;
        g_znlast[gb*64 + tid]   = zn7;
    }
    if (wid < 7){
        int r = wid;
        float iz1 = 1.f / fmaxf(sqrtf(sm[ONRM + r*4]), 1e-8f);
        float iz2 = 1.f / fmaxf(sqrtf(sm[ONRM + (r+1)*4]), 1e-8f);
        float d = sm[OZR + r*64 + lane]      * sm[OZR + (r+1)*64 + lane]
                + sm[OZR + r*64 + lane + 32] * sm[OZR + (r+1)*64 + lane + 32];
        #pragma unroll
        for (int s = 16; s > 0; s >>= 1) d += __shfl_down_sync(0xffffffffu, d, s);
        if (lane == 0){
            float dd = 1.f - d*iz1*iz2;
            sm[ORED + r] = dd*dd;
        }
    }
    __syncthreads();
    if (tid == 0){
        float ts = 0.f;
        #pragma unroll
        for (int r = 0; r < 7; r++) ts += sm[ORED + r];
        g_timepart[gb] = ts;
    }
}

// ================ KERNEL B: cross pairs + tensor logits + final ============
__global__ void __launch_bounds__(256, 2)
logits_kernel(float* __restrict__ out)
{
    extern __shared__ float sm[];
    __shared__ unsigned int lastFlag;

    const int tid  = threadIdx.x;
    const int bid  = blockIdx.x;
    const int G    = gridDim.x;
    const int lane = tid & 31;
    const int wid  = tid >> 5;
    const int c    = tid & 63;
    const int quad = tid >> 6;

    // cross time-pair for group bid
    {
        int gb = bid;
        if ((gb & 63) != 63 && wid == 0){
            float d = g_znlast[gb*64 + lane]      * g_znfirst[(gb+1)*64 + lane]
                    + g_znlast[gb*64 + lane + 32] * g_znfirst[(gb+1)*64 + lane + 32];
            #pragma unroll
            for (int s = 16; s > 0; s >>= 1) d += __shfl_down_sync(0xffffffffu, d, s);
            if (lane == 0){
                float dd = 1.f - d;
                g_timepart[gb] += dd*dd;
            }
        }
    }

    // logits tile: 128x128; warp = 16 rows x 128 cols
    {
        const int rb = (bid & 15) << 7, cb = (bid >> 4) << 7;

        // stage B fragments: pure copy from precomputed g_kfrag
        {
            float4* BV = (float4*)sm;
            #pragma unroll
            for (int it = 0; it < 16; it++){
                int e = it*256 + tid;
                int n = e >> 8, S = (e >> 5) & 7, colq = (e >> 2) & 7, j = e & 3;
                BV[e] = g_kfrag[(cb + n*8 + colq)*32 + S*4 + j];
            }
        }
        __syncthreads();

        float acc[16][4];
        #pragma unroll
        for (int n = 0; n < 16; n++){
            acc[n][0] = 0.f; acc[n][1] = 0.f; acc[n][2] = 0.f; acc[n][3] = 0.f;
        }

        // A fragments: 2 x LDG.128 per S (rows r and r+8)
        const float4* qf = &g_qfrag[(rb + wid*16 + (lane >> 2))*32 + (lane & 3)];
        const float4* BV = (const float4*)sm;

        #pragma unroll 2
        for (int S = 0; S < 8; S++){
            float4 f0 = qf[S*4];            // row r
            float4 f1 = qf[8*32 + S*4];     // row r+8
            float4 ah = make_float4(f0.x, f1.x, f0.y, f1.y);
            float4 al = make_float4(f0.z, f1.z, f0.w, f1.w);
            #pragma unroll
            for (int n = 0; n < 16; n++){
                float4 bb = BV[(n*8 + S)*32 + lane];
                uint32_t b0h = __float_as_uint(bb.x), b1h = __float_as_uint(bb.y);
                uint32_t b0l = __float_as_uint(bb.z), b1l = __float_as_uint(bb.w);
                mma8(acc[n], ah, b0h, b1h);
                mma8(acc[n], ah, b0l, b1l);
                mma8(acc[n], al, b0h, b1h);
            }
        }

        // epilogue: exp + row/col sums
        float* colPart = sm + CPART;
        float rlo = 0.f, rhi = 0.f;
        #pragma unroll
        for (int n = 0; n < 16; n++){
            float e0 = fexp(acc[n][0] * 10.f);
            float e1 = fexp(acc[n][1] * 10.f);
            float e2 = fexp(acc[n][2] * 10.f);
            float e3 = fexp(acc[n][3] * 10.f);
            rlo += e0 + e1; rhi += e2 + e3;
            float ca = e0 + e2, cbv = e1 + e3;
            #pragma unroll
            for (int o = 4; o < 32; o <<= 1){
                ca  += __shfl_xor_sync(0xffffffffu, ca,  o);
                cbv += __shfl_xor_sync(0xffffffffu, cbv, o);
            }
            if (lane < 4){
                colPart[wid*128 + n*8 + 2*lane]     = ca;
                colPart[wid*128 + n*8 + 2*lane + 1] = cbv;
            }
        }
        rlo += __shfl_xor_sync(0xffffffffu, rlo, 1);
        rlo += __shfl_xor_sync(0xffffffffu, rlo, 2);
        rhi += __shfl_xor_sync(0xffffffffu, rhi, 1);
        rhi += __shfl_xor_sync(0xffffffffu, rhi, 2);
        if ((lane & 3) == 0){
            atomicAdd(&g_rowsum[rb + wid*16 + (lane >> 2)],     rlo);
            atomicAdd(&g_rowsum[rb + wid*16 + 8 + (lane >> 2)], rhi);
        }
        __syncthreads();
        if (tid < 128){
            float s2 = 0.f;
            #pragma unroll
            for (int w2 = 0; w2 < 8; w2++) s2 += colPart[w2*128 + tid];
            atomicAdd(&g_colsum[cb + tid], s2);
        }
    }

    // ---- final combine: last block ----
    __threadfence();
    __syncthreads();
    if (tid == 0){
        unsigned t = atomicAdd(&g_done, 1u);
        lastFlag = (t == (unsigned)G - 1u) ? 1u : 0u;
    }
    __syncthreads();
    if (lastFlag){
        float ms = 0.f;
        for (int blk = quad; blk < 256; blk += 4)
            ms += __ldcg(&g_meanpart[blk*64 + c]);
        __syncthreads();
        sm[tid] = ms;
        __syncthreads();
        if (tid < 64){
            float Mv = sm[tid] + sm[64+tid] + sm[128+tid] + sm[192+tid];
            sm[256 + tid] = Mv*Mv;
        }
        __syncthreads();

        float tv = __ldcg(&g_timepart[tid]);
        float s = 0.f;
        for (int r = tid; r < 2048; r += 256)
            s += __logf(__ldcg(&g_rowsum[r])) + __logf(__ldcg(&g_colsum[r]))
               - 2.f*__ldcg(&g_diag[r]);
        sm[512 + tid] = tv;
        sm[768 + tid] = s;
        __syncthreads();
        for (int st = 128; st > 0; st >>= 1){
            if (tid < st){
                sm[512+tid] += sm[512+tid+st];
                sm[768+tid] += sm[768+tid+st];
            }
            __syncthreads();
        }
        if (tid == 0){
            float nm2 = 0.f;
            #pragma unroll
            for (int i = 0; i < 64; i++) nm2 += sm[256 + i];
            float normM = sqrtf(nm2);
            float l_con = 0.5f * sm[768] / 2048.f;
            float l_sc  = -normM / 2048.f;
            float l_t   =  sm[512] / 2044.f;
            out[0] = l_con + l_sc + l_t;
            out[1] = l_con;
            out[2] = l_sc;
            out[3] = l_t;
            g_done = 0;   // reset for next graph replay
        }
    }
}

// ---------------- launch ----------------
extern "C" void kernel_launch(void* const* d_in, const int* in_sizes, int n_in,
                              void* d_out, int out_size){
    const float* h      = (const float*)d_in[0];
    const float* x_raw  = (const float*)d_in[1];
    const float* W_in   = (const float*)d_in[2];
    const float* b_in   = (const float*)d_in[3];
    const float* dt_emb = (const float*)d_in[4];
    const float* Wm1    = (const float*)d_in[5];
    const float* bm1    = (const float*)d_in[6];
    const float* Wm2    = (const float*)d_in[7];
    const float* bm2    = (const float*)d_in[8];
    const float* Wg     = (const float*)d_in[9];
    const float* a1     = (const float*)d_in[10];
    const float* a2     = (const float*)d_in[11];
    const float* Wf     = (const float*)d_in[12];
    const float* bf     = (const float*)d_in[13];
    float* out = (float*)d_out;

    const int SMA = SMEMA * 4;
    const int SMB = SMEMB * 4;
    cudaFuncSetAttribute(feat_kernel,   cudaFuncAttributeMaxDynamicSharedMemorySize, SMA);
    cudaFuncSetAttribute(logits_kernel, cudaFuncAttributeMaxDynamicSharedMemorySize, SMB);

    feat_kernel<<<256, 256, SMA>>>(h, x_raw, W_in, b_in, dt_emb, Wm1, bm1, Wm2,
                                   bm2, Wg, a1, a2, Wf, bf);
    logits_kernel<<<256, 256, SMB>>>(out);
}